// round 5
// baseline (speedup 1.0000x reference)
#include <cuda_runtime.h>
#include <cstddef>
#include <cstdint>

#define F 32
#define P 16

// Flag written by the dtype-detection prepass: 1 if idx/widx are int64, 0 if int32.
__device__ unsigned g_is64;

// jax silently downgrades int64->int32 when x64 is disabled, so the stored dtype
// of idx/widx is environment-dependent. Indices are < 2*M = 400000 < 2^31, so if
// the buffer is int64 every odd 32-bit word (the high half) is exactly 0.
// P(false positive | int32 data) ~ (2.5e-6)^64 ~ 0. Deterministic per input.
__global__ void detect_dtype_kernel(const unsigned* __restrict__ raw) {
    if (threadIdx.x == 0 && blockIdx.x == 0) {
        unsigned acc = 0u;
        #pragma unroll
        for (int i = 0; i < 64; ++i) acc |= raw[2 * i + 1];
        g_is64 = (acc == 0u) ? 1u : 0u;
    }
}

// Single-line gather: 4 predicated LDG.128s, each with exactly one 8-lane group
// active (one 128B line -> one L1 wavefront at the cross-LDG 1.0 cyc/wf rate),
// instead of one LDG.128 spanning 4 lines (within-LDG replay ~2x cost).
// Predicates are lane-disjoint, so all four loads may share dest registers:
// exactly one load writes per lane.
__device__ __forceinline__ float4 gather_row_1line(const float4* ptr, unsigned grp) {
    float4 v;
    asm volatile(
        "{\n\t"
        ".reg .pred q0, q1, q2, q3;\n\t"
        "setp.eq.u32 q0, %5, 0;\n\t"
        "setp.eq.u32 q1, %5, 1;\n\t"
        "setp.eq.u32 q2, %5, 2;\n\t"
        "setp.eq.u32 q3, %5, 3;\n\t"
        "@q0 ld.global.nc.v4.f32 {%0,%1,%2,%3}, [%4];\n\t"
        "@q1 ld.global.nc.v4.f32 {%0,%1,%2,%3}, [%4];\n\t"
        "@q2 ld.global.nc.v4.f32 {%0,%1,%2,%3}, [%4];\n\t"
        "@q3 ld.global.nc.v4.f32 {%0,%1,%2,%3}, [%4];\n\t"
        "}"
        : "=f"(v.x), "=f"(v.y), "=f"(v.z), "=f"(v.w)
        : "l"(ptr), "r"(grp));
    return v;
}

// 4 neurons per warp, 8 lanes per neuron, float4 (4 feature columns) per lane.
__global__ __launch_bounds__(256)
void linear_gather_kernel(const float* __restrict__ values0,
                          const float* __restrict__ values1,
                          const float* __restrict__ w_table,
                          const void*  __restrict__ idx_raw,
                          const void*  __restrict__ widx_raw,
                          float* __restrict__ out,
                          int N, int M) {
    const unsigned is64 = g_is64;
    const int warp = (blockIdx.x * blockDim.x + threadIdx.x) >> 5;
    const int lane = threadIdx.x & 31;
    const int sub  = lane & 7;             // lane within the neuron's 8-lane group
    const unsigned grp = (unsigned)(lane >> 3);
    const int nb   = warp * 4;
    int n = nb + (int)grp;                 // this group's neuron
    if (nb >= N) return;
    const bool valid = (n < N);
    if (!valid) n = N - 1;                 // clamp for loads; store is predicated

    // ---- preload: 2 indices + 2 weights per lane (16 per 8-lane group) ----
    int ia, ib;                            // idx[n*16 + 2*sub], idx[n*16 + 2*sub+1]
    long long wrow;
    if (is64) {
        const longlong2 L =
            ((const longlong2*)idx_raw)[(size_t)n * (P / 2) + sub];
        ia = (int)L.x; ib = (int)L.y;
        wrow = ((const long long*)widx_raw)[n];
    } else {
        const int2 L = ((const int2*)idx_raw)[(size_t)n * (P / 2) + sub];
        ia = L.x; ib = L.y;
        wrow = ((const int*)widx_raw)[n];
    }
    const float2 w2 =
        ((const float2*)(w_table + (size_t)wrow * P))[sub];   // w[2sub], w[2sub+1]

    // Per-lane feature base pointers (sub*4 columns), values1 pre-shifted by -M rows
    const float* __restrict__ base0 = values0 + sub * 4;
    const float* __restrict__ base1 = values1 + sub * 4 - (size_t)M * F;

    float4 acc = make_float4(0.f, 0.f, 0.f, 0.f);

    #pragma unroll
    for (int p = 0; p < P; ++p) {
        // broadcast within the 8-lane partition; source lane p/2 is an immediate
        const int   ip = (p & 1) ? __shfl_sync(0xffffffffu, ib, p >> 1, 8)
                                 : __shfl_sync(0xffffffffu, ia, p >> 1, 8);
        const float wp = (p & 1) ? __shfl_sync(0xffffffffu, w2.y, p >> 1, 8)
                                 : __shfl_sync(0xffffffffu, w2.x, p >> 1, 8);
        const float* src = (ip < M) ? base0 : base1;
        const float4 v = gather_row_1line(
            (const float4*)(src + (size_t)ip * F), grp);
        acc.x = fmaf(wp, v.x, acc.x);
        acc.y = fmaf(wp, v.y, acc.y);
        acc.z = fmaf(wp, v.z, acc.z);
        acc.w = fmaf(wp, v.w, acc.w);
    }

    if (valid)
        ((float4*)out)[(size_t)n * (F / 4) + sub] = acc;
}

extern "C" void kernel_launch(void* const* d_in, const int* in_sizes, int n_in,
                              void* d_out, int out_size) {
    // metadata order: values0 [M,F] f32, values1 [M,F] f32, w_table [K,P] f32,
    //                 idx [N,P] int64/int32, widx [N] int64/int32
    const float* values0 = (const float*)d_in[0];
    const float* values1 = (const float*)d_in[1];
    const float* w_table = (const float*)d_in[2];
    const void*  idx     = d_in[3];
    const void*  widx    = d_in[4];
    float* out = (float*)d_out;

    const int M = in_sizes[0] / F;   // rows per source layer
    const int N = in_sizes[4];       // output neurons (widx element count)

    detect_dtype_kernel<<<1, 32>>>((const unsigned*)idx);

    const int threads = 256;                       // 8 warps = 32 neurons/block
    const int neurons_per_block = (threads / 32) * 4;
    const int blocks = (N + neurons_per_block - 1) / neurons_per_block;
    linear_gather_kernel<<<blocks, threads>>>(values0, values1, w_table,
                                              idx, widx, out, N, M);
}

// round 6
// speedup vs baseline: 4.9924x; 4.9924x over previous
#include <cuda_runtime.h>
#include <cstddef>

#define F 32
#define P 16

// 4 neurons per warp, 8 lanes per neuron, float4 (4 feature columns) per lane.
// Gathers issued in independent batches of 4 (separate dest regs) so the L1
// pipe stays saturated; idx/w broadcast via width-8 partition shuffles.
__global__ __launch_bounds__(256)
void linear_gather_kernel(const float* __restrict__ values0,
                          const float* __restrict__ values1,
                          const float* __restrict__ w_table,
                          const void*  __restrict__ idx_raw,
                          const void*  __restrict__ widx_raw,
                          float* __restrict__ out,
                          int N, int M) {
    // ---- dtype detection, folded into the kernel (one warp per block) ----
    // jax silently downgrades int64->int32 when x64 is off. Indices < 2^31,
    // so for int64 every odd 32-bit word is exactly 0. Sample 64 odd words
    // (same words in every block -> uniform, deterministic).
    __shared__ unsigned s_is64;
    if (threadIdx.x < 32) {
        const unsigned* raw = (const unsigned*)idx_raw;
        const unsigned v = raw[2 * threadIdx.x + 1] | raw[64 + 2 * threadIdx.x + 1];
        const unsigned any = __ballot_sync(0xffffffffu, v != 0u);
        if (threadIdx.x == 0) s_is64 = (any == 0u) ? 1u : 0u;
    }
    __syncthreads();
    const unsigned is64 = s_is64;

    const int warp = (blockIdx.x * blockDim.x + threadIdx.x) >> 5;
    const int lane = threadIdx.x & 31;
    const int sub  = lane & 7;            // lane within the neuron's 8-lane group
    const int nb   = warp * 4;
    int n = nb + (lane >> 3);             // this group's neuron
    if (nb >= N) return;
    const bool valid = (n < N);
    if (!valid) n = N - 1;                // clamp for loads; store is predicated

    // ---- preload: 2 indices + 2 weights per lane (16 per 8-lane group) ----
    int ia, ib;                           // idx[n*16 + 2*sub], idx[n*16 + 2*sub+1]
    long long wrow;
    if (is64) {
        const longlong2 L =
            ((const longlong2*)idx_raw)[(size_t)n * (P / 2) + sub];
        ia = (int)L.x; ib = (int)L.y;
        wrow = ((const long long*)widx_raw)[n];
    } else {
        const int2 L = ((const int2*)idx_raw)[(size_t)n * (P / 2) + sub];
        ia = L.x; ib = L.y;
        wrow = ((const int*)widx_raw)[n];
    }
    const float2 w2 =
        ((const float2*)(w_table + (size_t)wrow * P))[sub];   // w[2sub], w[2sub+1]

    // Per-lane feature base pointers (sub*4 cols), values1 pre-shifted by -M rows
    const float* __restrict__ base0 = values0 + sub * 4;
    const float* __restrict__ base1 = values1 + sub * 4 - (size_t)M * F;

    float4 acc = make_float4(0.f, 0.f, 0.f, 0.f);

    #pragma unroll
    for (int c = 0; c < P / 4; ++c) {
        // broadcast 4 (idx, w) pairs for this quad; src lane is an immediate
        int   ip[4];
        float wp[4];
        #pragma unroll
        for (int q = 0; q < 4; ++q) {
            const int p = c * 4 + q;
            ip[q] = (p & 1) ? __shfl_sync(0xffffffffu, ib, p >> 1, 8)
                            : __shfl_sync(0xffffffffu, ia, p >> 1, 8);
            wp[q] = (p & 1) ? __shfl_sync(0xffffffffu, w2.y, p >> 1, 8)
                            : __shfl_sync(0xffffffffu, w2.x, p >> 1, 8);
        }
        // 4 independent gathers in flight (separate dest regs, no WAW)
        const float4* a0 = (const float4*)(((ip[0] < M) ? base0 : base1) + (size_t)ip[0] * F);
        const float4* a1 = (const float4*)(((ip[1] < M) ? base0 : base1) + (size_t)ip[1] * F);
        const float4* a2 = (const float4*)(((ip[2] < M) ? base0 : base1) + (size_t)ip[2] * F);
        const float4* a3 = (const float4*)(((ip[3] < M) ? base0 : base1) + (size_t)ip[3] * F);
        const float4 v0 = __ldg(a0);
        const float4 v1 = __ldg(a1);
        const float4 v2 = __ldg(a2);
        const float4 v3 = __ldg(a3);

        acc.x = fmaf(wp[0], v0.x, acc.x);
        acc.y = fmaf(wp[0], v0.y, acc.y);
        acc.z = fmaf(wp[0], v0.z, acc.z);
        acc.w = fmaf(wp[0], v0.w, acc.w);
        acc.x = fmaf(wp[1], v1.x, acc.x);
        acc.y = fmaf(wp[1], v1.y, acc.y);
        acc.z = fmaf(wp[1], v1.z, acc.z);
        acc.w = fmaf(wp[1], v1.w, acc.w);
        acc.x = fmaf(wp[2], v2.x, acc.x);
        acc.y = fmaf(wp[2], v2.y, acc.y);
        acc.z = fmaf(wp[2], v2.z, acc.z);
        acc.w = fmaf(wp[2], v2.w, acc.w);
        acc.x = fmaf(wp[3], v3.x, acc.x);
        acc.y = fmaf(wp[3], v3.y, acc.y);
        acc.z = fmaf(wp[3], v3.z, acc.z);
        acc.w = fmaf(wp[3], v3.w, acc.w);
    }

    if (valid)
        ((float4*)out)[(size_t)n * (F / 4) + sub] = acc;
}

extern "C" void kernel_launch(void* const* d_in, const int* in_sizes, int n_in,
                              void* d_out, int out_size) {
    // metadata order: values0 [M,F] f32, values1 [M,F] f32, w_table [K,P] f32,
    //                 idx [N,P] int64/int32, widx [N] int64/int32
    const float* values0 = (const float*)d_in[0];
    const float* values1 = (const float*)d_in[1];
    const float* w_table = (const float*)d_in[2];
    const void*  idx     = d_in[3];
    const void*  widx    = d_in[4];
    float* out = (float*)d_out;

    const int M = in_sizes[0] / F;   // rows per source layer
    const int N = in_sizes[4];       // output neurons (widx element count)

    const int threads = 256;                       // 8 warps = 32 neurons/block
    const int neurons_per_block = (threads / 32) * 4;
    const int blocks = (N + neurons_per_block - 1) / neurons_per_block;
    linear_gather_kernel<<<blocks, threads>>>(values0, values1, w_table,
                                              idx, widx, out, N, M);
}